// round 3
// baseline (speedup 1.0000x reference)
#include <cuda_runtime.h>
#include <math.h>

// Problem constants
#define B_   2
#define L_   128
#define LY_  16
#define E_   256
#define V_   32000
#define C_   18        // 2 static + LY dynamic mixture components

// Distinct candidate rows: 0..255 emit(b,l), 256..511 z(b,l), 512..543 y(b,j)
#define R_      544
#define RPAD    576    // padded to 9 * 64
#define BM      64
#define BN      128
#define BK      32
#define NVT     250    // V_/BN
#define NMT     9      // RPAD/BM
#define NVT_PAD 256

// ---- scratch (device globals; no allocation allowed) ----
__device__ float g_cand[RPAD * E_];            // candidate rows
__device__ float g_xkey[B_ * C_ * E_];         // mixture keys
__device__ float g_partial[RPAD * NVT_PAD];    // per (row, vtile) sum-exp partials
__device__ float g_logZ[RPAD];                 // log softmax normalizer per row
__device__ float g_negcent[B_ * L_];           // -cent per (b,l)
__device__ int   g_yt64;                       // 1 if yt is int64, 0 if int32

// ---------------------------------------------------------------------------
// Detect yt dtype (int64 vs int32). Under int64 (little-endian, values <2^31),
// every odd int32 word of the first 256 words is zero. Under int32 that is
// astronomically unlikely. Only reads the first 256 int32 words (in-bounds in
// both cases).
// ---------------------------------------------------------------------------
__global__ void k_detect(const int* __restrict__ yt32) {
    __shared__ int ok;
    int tid = threadIdx.x;
    if (tid == 0) ok = 1;
    __syncthreads();
    if (tid < 128 && yt32[2 * tid + 1] != 0) atomicExch(&ok, 0);
    __syncthreads();
    if (tid == 0) g_yt64 = ok;
}

// ---------------------------------------------------------------------------
// Copy z and y into candidate rows, zero pad rows, install static keys.
// ---------------------------------------------------------------------------
__global__ void k_copy(const float* __restrict__ z,
                       const float* __restrict__ y,
                       const float* __restrict__ Wst) {
    int i = blockIdx.x * blockDim.x + threadIdx.x;   // 0 .. 65535
    if (i < B_ * L_ * E_)  g_cand[256 * E_ + i] = z[i];
    if (i < B_ * LY_ * E_) g_cand[512 * E_ + i] = y[i];
    if (i < (RPAD - R_) * E_) g_cand[R_ * E_ + i] = 0.f;
    if (i < 2 * E_) {                     // static key rows for both batches
        g_xkey[i] = Wst[i];               // b=0, c=0,1
        g_xkey[C_ * E_ + i] = Wst[i];     // b=1, c=0,1
    }
}

// ---------------------------------------------------------------------------
// Small NT GEMM with bias: Out[m][n] = bias[n] + sum_k A[m][k] * W[n][k]
// mode 0: emit = xsa @ W_emit^T + b_emit  -> g_cand rows [0,256)
// mode 1: dyn keys = y @ W_dyn^T + b_dyn  -> g_xkey rows (b, 2+j)
// ---------------------------------------------------------------------------
__global__ void __launch_bounds__(256) k_gemm_nt(const float* __restrict__ A,
                                                 const float* __restrict__ W,
                                                 const float* __restrict__ bias,
                                                 int mode) {
    __shared__ float As[16][17];
    __shared__ float Ws[16][17];
    int tx = threadIdx.x, ty = threadIdx.y;
    int m = blockIdx.y * 16 + ty;
    int n = blockIdx.x * 16 + tx;
    float acc = 0.f;
    for (int k0 = 0; k0 < E_; k0 += 16) {
        As[ty][tx] = A[m * E_ + k0 + tx];
        Ws[ty][tx] = W[(blockIdx.x * 16 + ty) * E_ + k0 + tx];
        __syncthreads();
#pragma unroll
        for (int kk = 0; kk < 16; ++kk) acc = fmaf(As[ty][kk], Ws[tx][kk], acc);
        __syncthreads();
    }
    acc += bias[n];
    if (mode == 0) {
        g_cand[m * E_ + n] = acc;
    } else {
        int b = m >> 4, j = m & 15;
        g_xkey[(b * C_ + 2 + j) * E_ + n] = acc;
    }
}

// ---------------------------------------------------------------------------
// Main fused kernel: logits = Cand(64-row tile) x Embed^T(128-vocab tile),
// epilogue sum_v exp(logit) -> g_partial. Swizzled smem (128B XOR) for
// conflict-free float4 fragments; 4x8 micro-tile per thread.
// ---------------------------------------------------------------------------
__global__ void __launch_bounds__(256, 2) k_main(const float* __restrict__ embed) {
    const int vt = blockIdx.x;   // 0..249
    const int mt = blockIdx.y;   // 0..8
    __shared__ float As[BM * BK];           // [m][k], 128B rows, swizzled
    __shared__ float Bs[BN * BK];
    __shared__ float pss[BM * 17];          // deterministic row reduction
    const int tid = threadIdx.x;
    const int r0 = tid & 15;                // rows  r0 + 16*i, i<4
    const int c0 = tid >> 4;                // cols  c0 + 16*j, j<8

    float acc[4][8];
#pragma unroll
    for (int i = 0; i < 4; ++i)
#pragma unroll
        for (int j = 0; j < 8; ++j) acc[i][j] = 0.f;

    const float* Abase = g_cand + (size_t)mt * BM * E_;
    const float* Bbase = embed + (size_t)vt * BN * E_;

    for (int kt = 0; kt < E_ / BK; ++kt) {
        const int kofs = kt * BK;
        // A tile: 64x32 = 512 float4, 2 per thread, coalesced LDG / swizzled STS
#pragma unroll
        for (int t = 0; t < 2; ++t) {
            int lin = tid + t * 256;
            int m = lin >> 3, k4 = lin & 7;
            float4 v = *reinterpret_cast<const float4*>(Abase + m * E_ + kofs + k4 * 4);
            *reinterpret_cast<float4*>(As + m * BK + ((k4 ^ (m & 7)) << 2)) = v;
        }
        // B tile: 128x32 = 1024 float4, 4 per thread
#pragma unroll
        for (int t = 0; t < 4; ++t) {
            int lin = tid + t * 256;
            int n = lin >> 3, k4 = lin & 7;
            float4 v = *reinterpret_cast<const float4*>(Bbase + n * E_ + kofs + k4 * 4);
            *reinterpret_cast<float4*>(Bs + n * BK + ((k4 ^ (n & 7)) << 2)) = v;
        }
        __syncthreads();
#pragma unroll
        for (int k4 = 0; k4 < 8; ++k4) {
            float4 a[4], b[8];
#pragma unroll
            for (int i = 0; i < 4; ++i) {
                int m = r0 + i * 16;
                a[i] = *reinterpret_cast<const float4*>(As + m * BK + ((k4 ^ (m & 7)) << 2));
            }
#pragma unroll
            for (int j = 0; j < 8; ++j) {
                int n = c0 + j * 16;
                b[j] = *reinterpret_cast<const float4*>(Bs + n * BK + ((k4 ^ (n & 7)) << 2));
            }
#pragma unroll
            for (int i = 0; i < 4; ++i)
#pragma unroll
                for (int j = 0; j < 8; ++j) {
                    acc[i][j] = fmaf(a[i].x, b[j].x, acc[i][j]);
                    acc[i][j] = fmaf(a[i].y, b[j].y, acc[i][j]);
                    acc[i][j] = fmaf(a[i].z, b[j].z, acc[i][j]);
                    acc[i][j] = fmaf(a[i].w, b[j].w, acc[i][j]);
                }
        }
        __syncthreads();
    }

    // Epilogue: per-row partial sum of exp(logit). Logits are O(1) for this
    // problem (|logit| < ~30 worst case), so a shift-free fp32 exp-sum is safe.
#pragma unroll
    for (int i = 0; i < 4; ++i) {
        float ps = 0.f;
#pragma unroll
        for (int j = 0; j < 8; ++j) ps += __expf(acc[i][j]);
        pss[(r0 + i * 16) * 17 + c0] = ps;
    }
    __syncthreads();
    if (tid < BM) {
        float s = 0.f;
#pragma unroll
        for (int c = 0; c < 16; ++c) s += pss[tid * 17 + c];
        g_partial[(mt * BM + tid) * NVT_PAD + vt] = s;
    }
}

// ---------------------------------------------------------------------------
// Reduce per-row vocab-tile partials -> logZ[row] = log(sum_v exp(logit))
// ---------------------------------------------------------------------------
__global__ void k_reduceZ() {
    int row = blockIdx.x;
    int tid = threadIdx.x;
    float v = (tid < NVT) ? g_partial[row * NVT_PAD + tid] : 0.f;
#pragma unroll
    for (int o = 16; o > 0; o >>= 1) v += __shfl_xor_sync(0xffffffffu, v, o);
    __shared__ float sm[8];
    if ((tid & 31) == 0) sm[tid >> 5] = v;
    __syncthreads();
    if (tid == 0) {
        float s = 0.f;
#pragma unroll
        for (int w = 0; w < 8; ++w) s += sm[w];
        g_logZ[row] = logf(s);
    }
}

// ---------------------------------------------------------------------------
// Per (b,l): 18 selection-logit dots (xsa . xkey), 18 target-logit dots
// (embed[yt] . cand), then cent = LSE_c(sel + tl - logZ) - LSE_c(sel).
// ---------------------------------------------------------------------------
__global__ void __launch_bounds__(256) k_final(const float* __restrict__ xsa,
                                               const float* __restrict__ embed,
                                               const void* __restrict__ ytv) {
    int bl = blockIdx.x;            // 0..255
    int b = bl >> 7;
    int tid = threadIdx.x;

    long long t;
    if (g_yt64) t = ((const long long*)ytv)[bl];
    else        t = (long long)((const int*)ytv)[bl];

    float xv = xsa[bl * E_ + tid];
    float ev = embed[(size_t)t * E_ + tid];

    float sv[C_], tv[C_];
#pragma unroll
    for (int c = 0; c < C_; ++c)
        sv[c] = xv * g_xkey[(b * C_ + c) * E_ + tid];
    tv[0] = ev * g_cand[bl * E_ + tid];
    tv[1] = ev * g_cand[(256 + bl) * E_ + tid];
#pragma unroll
    for (int j = 0; j < LY_; ++j)
        tv[2 + j] = ev * g_cand[(512 + b * LY_ + j) * E_ + tid];

    __shared__ float red[2 * C_][9];
    int lane = tid & 31, w = tid >> 5;
#pragma unroll
    for (int c = 0; c < C_; ++c) {
        float v = sv[c];
#pragma unroll
        for (int o = 16; o > 0; o >>= 1) v += __shfl_xor_sync(0xffffffffu, v, o);
        if (lane == 0) red[c][w] = v;
    }
#pragma unroll
    for (int c = 0; c < C_; ++c) {
        float v = tv[c];
#pragma unroll
        for (int o = 16; o > 0; o >>= 1) v += __shfl_xor_sync(0xffffffffu, v, o);
        if (lane == 0) red[C_ + c][w] = v;
    }
    __syncthreads();

    if (tid == 0) {
        float s[C_], tl[C_];
#pragma unroll
        for (int c = 0; c < C_; ++c) {
            float a0 = 0.f, a1 = 0.f;
#pragma unroll
            for (int ww = 0; ww < 8; ++ww) { a0 += red[c][ww]; a1 += red[C_ + c][ww]; }
            s[c] = a0; tl[c] = a1;
        }
        float q[C_];
        q[0] = s[0] + tl[0] - g_logZ[bl];
        q[1] = s[1] + tl[1] - g_logZ[256 + bl];
#pragma unroll
        for (int j = 0; j < LY_; ++j)
            q[2 + j] = s[2 + j] + tl[2 + j] - g_logZ[512 + b * LY_ + j];

        float ms = s[0], mq = q[0];
#pragma unroll
        for (int c = 1; c < C_; ++c) { ms = fmaxf(ms, s[c]); mq = fmaxf(mq, q[c]); }
        float ss = 0.f, sq = 0.f;
#pragma unroll
        for (int c = 0; c < C_; ++c) { ss += expf(s[c] - ms); sq += expf(q[c] - mq); }
        float lse_s = ms + logf(ss);
        float lse_q = mq + logf(sq);
        g_negcent[bl] = -(lse_q - lse_s);
    }
}

// ---------------------------------------------------------------------------
// Final reduction: out[b] = mean_l (-cent)
// ---------------------------------------------------------------------------
__global__ void k_out(float* __restrict__ out) {
    __shared__ float sm[B_ * L_];
    int tid = threadIdx.x;
    sm[tid] = g_negcent[tid];
    __syncthreads();
    if (tid < B_) {
        float s = 0.f;
        for (int i = 0; i < L_; ++i) s += sm[tid * L_ + i];
        out[tid] = s / (float)L_;
    }
}

// ---------------------------------------------------------------------------
extern "C" void kernel_launch(void* const* d_in, const int* in_sizes, int n_in,
                              void* d_out, int out_size) {
    const float* xsa   = (const float*)d_in[0];
    const float* z     = (const float*)d_in[1];
    const float* y     = (const float*)d_in[2];
    const void*  yt    = d_in[3];
    const float* embed = (const float*)d_in[4];
    const float* Wst   = (const float*)d_in[5];
    const float* Wdyn  = (const float*)d_in[6];
    const float* bdyn  = (const float*)d_in[7];
    const float* Wemit = (const float*)d_in[8];
    const float* bemit = (const float*)d_in[9];
    float* out = (float*)d_out;

    k_detect<<<1, 256>>>((const int*)yt);
    k_copy<<<256, 256>>>(z, y, Wst);
    dim3 blk(16, 16);
    k_gemm_nt<<<dim3(16, 16), blk>>>(xsa, Wemit, bemit, 0);  // emit rows
    k_gemm_nt<<<dim3(16, 2),  blk>>>(y,   Wdyn,  bdyn,  1);  // dynamic keys
    k_main<<<dim3(NVT, NMT), 256>>>(embed);
    k_reduceZ<<<RPAD, 256>>>();
    k_final<<<B_ * L_, 256>>>(xsa, embed, yt);
    k_out<<<1, 256>>>(out);
}

// round 5
// speedup vs baseline: 2.9508x; 2.9508x over previous
#include <cuda_runtime.h>
#include <cuda_bf16.h>
#include <math.h>
#include <stdint.h>

// ---------------- problem constants ----------------
#define B_   2
#define L_   128
#define LY_  16
#define E_   256
#define V_   32000
#define C_   18        // 2 static + LY dynamic mixture components

// Distinct candidate rows: 0..255 emit(b,l), 256..511 z(b,l), 512..543 y(b,j)
#define R_      544
#define RPAD    640    // 5 tiles of 128
#define BM      128
#define BN      128
#define NMT     5      // RPAD/BM
#define NVT     250    // V_/BN
#define NVT_PAD 256

#define TILE_BYTES 65536      // one 128-row x 256-k bf16 tile (blocked SW128)
#define CHUNK_BYTES 16384     // one k64 chunk (128 rows x 128B)
#define SMEM_REQ   135168     // 1023 slack + 1024 ctrl + 2*64KB tiles + 2KB pss

// ---------------- device scratch (no allocation allowed) ----------------
__device__ float    g_cand[RPAD * E_];
__device__ float    g_xkey[B_ * C_ * E_];
__device__ float    g_partial[RPAD * NVT_PAD];
__device__ float    g_logZ[R_];
__device__ float    g_negcent[B_ * L_];
__device__ int      g_yt64;
__device__ uint32_t g_candb[NMT * TILE_BYTES / 4];          // cand bf16, swizzled
__device__ uint32_t g_ebf[(size_t)NVT * TILE_BYTES / 4];    // embed bf16, swizzled (16MB)

// ---------------- PTX helpers (plain sm_100-safe: sm_80/sm_90 features) ----
__device__ __forceinline__ uint32_t smem_u32(const void* p) {
    uint32_t a;
    asm("{ .reg .u64 t; cvta.to.shared.u64 t, %1; cvt.u32.u64 %0, t; }"
        : "=r"(a) : "l"(p));
    return a;
}
#define MBARRIER_INIT(mb, cnt) \
    asm volatile("mbarrier.init.shared.b64 [%0], %1;" :: "r"(mb), "r"((uint32_t)(cnt)) : "memory")
#define MBARRIER_EXPECT_TX(mb, bytes) \
    asm volatile("mbarrier.arrive.expect_tx.shared.b64 _, [%0], %1;" \
                 :: "r"(mb), "r"((uint32_t)(bytes)) : "memory")
#define MBARRIER_WAIT(mb, ph) do {                                              \
    uint32_t _mb = (mb), _ph = (ph), _done;                                     \
    asm volatile("{\n\t.reg .pred p;\n\t"                                       \
        "mbarrier.try_wait.parity.acquire.cta.shared::cta.b64 p, [%1], %2;\n\t" \
        "selp.b32 %0, 1, 0, p;\n\t}" : "=r"(_done) : "r"(_mb), "r"(_ph) : "memory"); \
    if (!_done) {                                                               \
        asm volatile("{\n\t.reg .pred P1;\n\t"                                  \
            "WL_%=:\n\t"                                                        \
            "mbarrier.try_wait.parity.acquire.cta.shared::cta.b64 P1, [%0], %1, 0x989680;\n\t" \
            "@P1 bra.uni WD_%=;\n\t"                                            \
            "bra.uni WL_%=;\n\t"                                                \
            "WD_%=:\n\t}" :: "r"(_mb), "r"(_ph) : "memory");                    \
    }                                                                           \
} while (0)
#define CP_ASYNC_BULK(dst, src, bytes, mb) \
    asm volatile("cp.async.bulk.shared::cluster.global.mbarrier::complete_tx::bytes " \
                 "[%0], [%1], %2, [%3];" \
                 :: "r"(dst), "l"(src), "r"((uint32_t)(bytes)), "r"(mb) : "memory")

#define LDSM_X4(r, addr) \
    asm volatile("ldmatrix.sync.aligned.m8n8.x4.shared.b16 {%0,%1,%2,%3}, [%4];" \
        : "=r"((r)[0]), "=r"((r)[1]), "=r"((r)[2]), "=r"((r)[3]) : "r"(addr))

#define MMA_BF16(c, a, b0, b1) \
    asm volatile("mma.sync.aligned.m16n8k16.row.col.f32.bf16.bf16.f32 " \
        "{%0,%1,%2,%3}, {%4,%5,%6,%7}, {%8,%9}, {%0,%1,%2,%3};" \
        : "+f"((c)[0]), "+f"((c)[1]), "+f"((c)[2]), "+f"((c)[3]) \
        : "r"((a)[0]), "r"((a)[1]), "r"((a)[2]), "r"((a)[3]), "r"(b0), "r"(b1))

__device__ __forceinline__ uint32_t pack_bf16(__nv_bfloat16 a, __nv_bfloat16 b) {
    __nv_bfloat162 t(a, b);   // .x = low half = element k, .y = element k+1
    return *reinterpret_cast<uint32_t*>(&t);
}

// ---------------------------------------------------------------------------
// Detect yt dtype (int64 vs int32) from zero-pattern of odd words (in-bounds
// read of 256 int32 words either way).
// ---------------------------------------------------------------------------
__global__ void k_detect(const int* __restrict__ yt32) {
    __shared__ int ok;
    int tid = threadIdx.x;
    if (tid == 0) ok = 1;
    __syncthreads();
    if (tid < 128 && yt32[2 * tid + 1] != 0) atomicExch(&ok, 0);
    __syncthreads();
    if (tid == 0) g_yt64 = ok;
}

// ---------------------------------------------------------------------------
// Copy z/y into candidate rows, zero pad rows 544..639, install static keys.
// ---------------------------------------------------------------------------
__global__ void k_copy(const float* __restrict__ z,
                       const float* __restrict__ y,
                       const float* __restrict__ Wst) {
    int i = blockIdx.x * blockDim.x + threadIdx.x;   // 0 .. 65535
    if (i < B_ * L_ * E_)  g_cand[256 * E_ + i] = z[i];
    if (i < B_ * LY_ * E_) g_cand[512 * E_ + i] = y[i];
    if (i < (RPAD - R_) * E_) g_cand[R_ * E_ + i] = 0.f;
    if (i < 2 * E_) {
        g_xkey[i] = Wst[i];               // b=0, c=0,1
        g_xkey[C_ * E_ + i] = Wst[i];     // b=1, c=0,1
    }
}

// ---------------------------------------------------------------------------
// Row-parallel NT GEMM + bias: one block per output row, one thread per col.
// mode 0: emit = xsa @ W_emit^T + b  -> g_cand rows [0,256)
// mode 1: dyn keys = y @ W_dyn^T + b -> g_xkey rows (b, 2+j)
// ---------------------------------------------------------------------------
__global__ void __launch_bounds__(256) k_rowgemm(const float* __restrict__ A,
                                                 const float* __restrict__ W,
                                                 const float* __restrict__ bias,
                                                 int mode) {
    __shared__ float4 As[E_ / 4];
    int m = blockIdx.x, n = threadIdx.x;
    if (n < E_ / 4) As[n] = reinterpret_cast<const float4*>(A + (size_t)m * E_)[n];
    __syncthreads();
    const float4* Wr = reinterpret_cast<const float4*>(W + (size_t)n * E_);
    float acc = bias[n];
#pragma unroll
    for (int k = 0; k < E_ / 4; ++k) {
        float4 w = Wr[k];
        float4 a = As[k];
        acc = fmaf(a.x, w.x, acc);
        acc = fmaf(a.y, w.y, acc);
        acc = fmaf(a.z, w.z, acc);
        acc = fmaf(a.w, w.w, acc);
    }
    if (mode == 0) {
        g_cand[(size_t)m * E_ + n] = acc;
    } else {
        int b = m >> 4, j = m & 15;
        g_xkey[(size_t)(b * C_ + 2 + j) * E_ + n] = acc;
    }
}

// ---------------------------------------------------------------------------
// Blocked SW128 tile layout (per 128-row tile, 256 k halves):
//   chunk c = k/64 at offset c*16384; within: row r at r*128 bytes; 16B unit
//   u = (k%64)/8 stored at unit (u ^ (r&7)).
// ---------------------------------------------------------------------------
__global__ void __launch_bounds__(256) k_convert(const float* __restrict__ embed) {
    int idx = blockIdx.x * 256 + threadIdx.x;          // 0 .. 4,095,999
    int v = idx >> 7;                                  // vocab row
    int q = idx & 127;                                 // bf16x2 pair index (k = 2q)
    float2 x = reinterpret_cast<const float2*>(embed)[(size_t)v * 128 + q];
    uint32_t w = pack_bf16(__float2bfloat16_rn(x.x), __float2bfloat16_rn(x.y));
    int vt = v >> 7, r = v & 127;
    int c = q >> 5;
    int boff = r * 128 + 4 * (q & 31);
    int sw = boff ^ ((boff >> 3) & 0x70);
    g_ebf[((size_t)vt * TILE_BYTES + (size_t)c * CHUNK_BYTES + sw) >> 2] = w;
}

__global__ void __launch_bounds__(256) k_aconv() {
    int idx = blockIdx.x * 256 + threadIdx.x;          // 0 .. 81919
    int row = idx >> 7;                                // cand row 0..639
    int q = idx & 127;
    float2 x = reinterpret_cast<const float2*>(g_cand)[(size_t)row * 128 + q];
    uint32_t w = pack_bf16(__float2bfloat16_rn(x.x), __float2bfloat16_rn(x.y));
    int mt = row >> 7, r = row & 127;
    int c = q >> 5;
    int boff = r * 128 + 4 * (q & 31);
    int sw = boff ^ ((boff >> 3) & 0x70);
    g_candb[((size_t)mt * TILE_BYTES + (size_t)c * CHUNK_BYTES + sw) >> 2] = w;
}

// ---------------------------------------------------------------------------
// Main GEMM+exp-sum kernel. CTA: 128(m cand) x 128(n vocab) x 256(k) bf16,
// 8 warps in 2m x 4n, warp tile 64x32 via mma.sync.m16n8k16. Operand tiles
// staged by 4x cp.async.bulk chunk pairs (prefetched), ldmatrix.x4 reads.
// ---------------------------------------------------------------------------
__global__ void __launch_bounds__(256, 1) k_main() {
    extern __shared__ __align__(16) char smem_raw[];
    uint32_t sb = smem_u32(smem_raw);
    uint32_t ab = (sb + 1023u) & ~1023u;
    uint32_t mb = ab;                       // 4 mbarriers @ +0,8,16,24
    uint32_t Abase = ab + 1024u;            // 64 KB
    uint32_t Bbase = Abase + TILE_BYTES;    // 64 KB
    float* pssf = reinterpret_cast<float*>(smem_raw + ((Bbase + TILE_BYTES) - sb));

    const int tid = threadIdx.x;
    const int lane = tid & 31, wid = tid >> 5;
    const int wm = wid & 1, wn = wid >> 1;
    const int mt = blockIdx.x;              // 0..4
    const int vt = blockIdx.y;              // 0..249

    if (tid == 0)
        for (int s = 0; s < 4; ++s) MBARRIER_INIT(mb + 8 * s, 1);
    __syncthreads();
    if (tid == 0) {
        const char* asrc = reinterpret_cast<const char*>(g_candb) + (size_t)mt * TILE_BYTES;
        const char* bsrc = reinterpret_cast<const char*>(g_ebf) + (size_t)vt * TILE_BYTES;
        for (int s = 0; s < 4; ++s) {
            MBARRIER_EXPECT_TX(mb + 8 * s, 2 * CHUNK_BYTES);
            CP_ASYNC_BULK(Abase + s * CHUNK_BYTES, asrc + s * CHUNK_BYTES, CHUNK_BYTES, mb + 8 * s);
            CP_ASYNC_BULK(Bbase + s * CHUNK_BYTES, bsrc + s * CHUNK_BYTES, CHUNK_BYTES, mb + 8 * s);
        }
    }

    float c[4][4][4];
#pragma unroll
    for (int mi = 0; mi < 4; ++mi)
#pragma unroll
        for (int nj = 0; nj < 4; ++nj)
#pragma unroll
            for (int e = 0; e < 4; ++e) c[mi][nj][e] = 0.f;

    // ldmatrix lane address parameters (see fragment layout comments)
    const int q = lane >> 3, j = lane & 7;
    const int a_row0 = wm * 64 + ((q & 1) << 3) + j;   // + mi*16
    const int a_kd = q >> 1;                           // 0/1: which k8 group
    const int b_row0 = wn * 32 + ((q & 2) << 2) + j;   // + p*16
    const int b_kd = q & 1;

#pragma unroll
    for (int s = 0; s < 16; ++s) {
        if ((s & 3) == 0) MBARRIER_WAIT(mb + 8 * (s >> 2), 0);
        const uint32_t Ac = Abase + (s >> 2) * CHUNK_BYTES;
        const uint32_t Bc = Bbase + (s >> 2) * CHUNK_BYTES;
        const int kg = (s & 3) * 2;

        uint32_t a[4][4];
#pragma unroll
        for (int mi = 0; mi < 4; ++mi) {
            int r = a_row0 + mi * 16;
            uint32_t addr = Ac + r * 128 + (((kg + a_kd) ^ (r & 7)) << 4);
            LDSM_X4(a[mi], addr);
        }
        uint32_t b[2][4];
#pragma unroll
        for (int p = 0; p < 2; ++p) {
            int r = b_row0 + p * 16;
            uint32_t addr = Bc + r * 128 + (((kg + b_kd) ^ (r & 7)) << 4);
            LDSM_X4(b[p], addr);
        }
#pragma unroll
        for (int mi = 0; mi < 4; ++mi)
#pragma unroll
            for (int p = 0; p < 2; ++p) {
                MMA_BF16(c[mi][2 * p],     a[mi], b[p][0], b[p][1]);
                MMA_BF16(c[mi][2 * p + 1], a[mi], b[p][2], b[p][3]);
            }
    }

    // Epilogue: per-row sum of exp(logit). Lane holds rows (g, g+8) of each
    // m16 tile at cols 2*t4, 2*t4+1 of each n8 tile.
    const int g = lane >> 2, t4 = lane & 3;
#pragma unroll
    for (int mi = 0; mi < 4; ++mi) {
        float sA = 0.f, sB = 0.f;
#pragma unroll
        for (int nj = 0; nj < 4; ++nj) {
            sA += __expf(c[mi][nj][0]) + __expf(c[mi][nj][1]);
            sB += __expf(c[mi][nj][2]) + __expf(c[mi][nj][3]);
        }
        sA += __shfl_xor_sync(0xffffffffu, sA, 1);
        sA += __shfl_xor_sync(0xffffffffu, sA, 2);
        sB += __shfl_xor_sync(0xffffffffu, sB, 1);
        sB += __shfl_xor_sync(0xffffffffu, sB, 2);
        if (t4 == 0) {
            int row = wm * 64 + mi * 16 + g;
            pssf[row * 4 + wn] = sA;
            pssf[(row + 8) * 4 + wn] = sB;
        }
    }
    __syncthreads();
    if (tid < BM) {
        float s = pssf[tid * 4] + pssf[tid * 4 + 1] + pssf[tid * 4 + 2] + pssf[tid * 4 + 3];
        g_partial[(size_t)(mt * BM + tid) * NVT_PAD + vt] = s;
    }
}

// ---------------------------------------------------------------------------
// Reduce per-row vocab-tile partials -> logZ[row]
// ---------------------------------------------------------------------------
__global__ void k_reduceZ() {
    int row = blockIdx.x;
    int tid = threadIdx.x;
    float v = (tid < NVT) ? g_partial[(size_t)row * NVT_PAD + tid] : 0.f;
#pragma unroll
    for (int o = 16; o > 0; o >>= 1) v += __shfl_xor_sync(0xffffffffu, v, o);
    __shared__ float sm[8];
    if ((tid & 31) == 0) sm[tid >> 5] = v;
    __syncthreads();
    if (tid == 0) {
        float s = 0.f;
#pragma unroll
        for (int w = 0; w < 8; ++w) s += sm[w];
        g_logZ[row] = logf(s);
    }
}

// ---------------------------------------------------------------------------
// Per (b,l): selection dots, target-logit dots, double LSE -> -cent
// ---------------------------------------------------------------------------
__global__ void __launch_bounds__(256) k_final(const float* __restrict__ xsa,
                                               const float* __restrict__ embed,
                                               const void* __restrict__ ytv) {
    int bl = blockIdx.x;            // 0..255
    int b = bl >> 7;
    int tid = threadIdx.x;

    long long t;
    if (g_yt64) t = ((const long long*)ytv)[bl];
    else        t = (long long)((const int*)ytv)[bl];

    float xv = xsa[(size_t)bl * E_ + tid];
    float ev = embed[(size_t)t * E_ + tid];

    float sv[C_], tv[C_];
#pragma unroll
    for (int c = 0; c < C_; ++c)
        sv[c] = xv * g_xkey[(size_t)(b * C_ + c) * E_ + tid];
    tv[0] = ev * g_cand[(size_t)bl * E_ + tid];
    tv[1] = ev * g_cand[(size_t)(256 + bl) * E_ + tid];
#pragma unroll
    for (int j = 0; j < LY_; ++j)
        tv[2 + j] = ev * g_cand[(size_t)(512 + b * LY_ + j) * E_ + tid];

    __shared__ float red[2 * C_][9];
    int lane = tid & 31, w = tid >> 5;
#pragma unroll
    for (int c = 0; c < C_; ++c) {
        float v = sv[c];
#pragma unroll
        for (int o = 16; o > 0; o >>= 1) v += __shfl_xor_sync(0xffffffffu, v, o);
        if (lane == 0) red[c][w] = v;
    }
#pragma unroll
    for (int c = 0; c < C_; ++c) {
        float v = tv[c];
#pragma unroll
        for (int o = 16; o > 0; o >>= 1) v += __shfl_xor_sync(0xffffffffu, v, o);
        if (lane == 0) red[C_ + c][w] = v;
    }
    __syncthreads();

    if (tid == 0) {
        float s[C_], tl[C_];
#pragma unroll
        for (int c = 0; c < C_; ++c) {
            float a0 = 0.f, a1 = 0.f;
#pragma unroll
            for (int ww = 0; ww < 8; ++ww) { a0 += red[c][ww]; a1 += red[C_ + c][ww]; }
            s[c] = a0; tl[c] = a1;
        }
        float qv[C_];
        qv[0] = s[0] + tl[0] - g_logZ[bl];
        qv[1] = s[1] + tl[1] - g_logZ[256 + bl];
#pragma unroll
        for (int j = 0; j < LY_; ++j)
            qv[2 + j] = s[2 + j] + tl[2 + j] - g_logZ[512 + b * LY_ + j];

        float ms = s[0], mq = qv[0];
#pragma unroll
        for (int c = 1; c < C_; ++c) { ms = fmaxf(ms, s[c]); mq = fmaxf(mq, qv[c]); }
        float ss = 0.f, sq = 0.f;
#pragma unroll
        for (int c = 0; c < C_; ++c) { ss += expf(s[c] - ms); sq += expf(qv[c] - mq); }
        g_negcent[bl] = -((mq + logf(sq)) - (ms + logf(ss)));
    }
}

// ---------------------------------------------------------------------------
__global__ void k_out(float* __restrict__ out) {
    __shared__ float sm[B_ * L_];
    int tid = threadIdx.x;
    sm[tid] = g_negcent[tid];
    __syncthreads();
    if (tid < B_) {
        float s = 0.f;
        for (int i = 0; i < L_; ++i) s += sm[tid * L_ + i];
        out[tid] = s / (float)L_;
    }
}

// ---------------------------------------------------------------------------
extern "C" void kernel_launch(void* const* d_in, const int* in_sizes, int n_in,
                              void* d_out, int out_size) {
    const float* xsa   = (const float*)d_in[0];
    const float* z     = (const float*)d_in[1];
    const float* y     = (const float*)d_in[2];
    const void*  yt    = d_in[3];
    const float* embed = (const float*)d_in[4];
    const float* Wst   = (const float*)d_in[5];
    const float* Wdyn  = (const float*)d_in[6];
    const float* bdyn  = (const float*)d_in[7];
    const float* Wemit = (const float*)d_in[8];
    const float* bemit = (const float*)d_in[9];
    float* out = (float*)d_out;

    cudaFuncSetAttribute(k_main, cudaFuncAttributeMaxDynamicSharedMemorySize,
                         SMEM_REQ);

    k_detect<<<1, 256>>>((const int*)yt);
    k_copy<<<256, 256>>>(z, y, Wst);
    k_rowgemm<<<256, 256>>>(xsa, Wemit, bemit, 0);   // emit rows
    k_rowgemm<<<32, 256>>>(y, Wdyn, bdyn, 1);        // dynamic keys
    k_aconv<<<320, 256>>>();                          // cand -> swizzled bf16
    k_convert<<<16000, 256>>>(embed);                 // embed -> swizzled bf16
    k_main<<<dim3(NMT, NVT), 256, SMEM_REQ>>>();
    k_reduceZ<<<R_, 256>>>();
    k_final<<<B_ * L_, 256>>>(xsa, embed, yt);
    k_out<<<1, 256>>>(out);
}

// round 6
// speedup vs baseline: 3.1900x; 1.0811x over previous
#include <cuda_runtime.h>
#include <cuda_bf16.h>
#include <math.h>
#include <stdint.h>

// ---------------- problem constants ----------------
#define B_   2
#define L_   128
#define LY_  16
#define E_   256
#define V_   32000
#define C_   18        // 2 static + LY dynamic mixture components

// Distinct candidate rows: 0..255 emit(b,l), 256..511 z(b,l), 512..543 y(b,j)
#define R_      544
#define RPAD    640    // 5 tiles of 128
#define BM      128
#define BN      128
#define NMT     5      // RPAD/BM
#define NVT     250    // V_/BN
#define NVT_PAD 256

#define TILE_BYTES  65536     // one 128-row x 256-k bf16 tile (blocked SW128)
#define CHUNK_BYTES 16384     // one k64 chunk (128 rows x 128B)
// 1023 slack + 1024 ctrl + A(64K) + B0(64K) + B1(64K) + pss(2K)
#define SMEM_REQ    200704

// ---------------- device scratch (no allocation allowed) ----------------
__device__ float    g_cand[RPAD * E_];
__device__ float    g_xkey[B_ * C_ * E_];
__device__ float    g_partial[RPAD * NVT_PAD];
__device__ float    g_logZ[R_];
__device__ float    g_negcent[B_ * L_];
__device__ int      g_yt64;
__device__ float    g_wtE[E_ * E_];                         // Wemit^T
__device__ float    g_wtD[E_ * E_];                         // Wdyn^T
__device__ uint32_t g_candb[NMT * TILE_BYTES / 4];          // cand bf16, swizzled
__device__ uint32_t g_ebf[(size_t)NVT * TILE_BYTES / 4];    // embed bf16, swizzled

// ---------------- PTX helpers (plain sm_100-safe) ----------
__device__ __forceinline__ uint32_t smem_u32(const void* p) {
    uint32_t a;
    asm("{ .reg .u64 t; cvta.to.shared.u64 t, %1; cvt.u32.u64 %0, t; }"
        : "=r"(a) : "l"(p));
    return a;
}
#define MBARRIER_INIT(mb, cnt) \
    asm volatile("mbarrier.init.shared.b64 [%0], %1;" :: "r"(mb), "r"((uint32_t)(cnt)) : "memory")
#define MBARRIER_EXPECT_TX(mb, bytes) \
    asm volatile("mbarrier.arrive.expect_tx.shared.b64 _, [%0], %1;" \
                 :: "r"(mb), "r"((uint32_t)(bytes)) : "memory")
#define MBARRIER_WAIT(mb, ph) do {                                              \
    uint32_t _mb = (mb), _ph = (ph), _done;                                     \
    asm volatile("{\n\t.reg .pred p;\n\t"                                       \
        "mbarrier.try_wait.parity.acquire.cta.shared::cta.b64 p, [%1], %2;\n\t" \
        "selp.b32 %0, 1, 0, p;\n\t}" : "=r"(_done) : "r"(_mb), "r"(_ph) : "memory"); \
    if (!_done) {                                                               \
        asm volatile("{\n\t.reg .pred P1;\n\t"                                  \
            "WL_%=:\n\t"                                                        \
            "mbarrier.try_wait.parity.acquire.cta.shared::cta.b64 P1, [%0], %1, 0x989680;\n\t" \
            "@P1 bra.uni WD_%=;\n\t"                                            \
            "bra.uni WL_%=;\n\t"                                                \
            "WD_%=:\n\t}" :: "r"(_mb), "r"(_ph) : "memory");                    \
    }                                                                           \
} while (0)
#define CP_ASYNC_BULK(dst, src, bytes, mb) \
    asm volatile("cp.async.bulk.shared::cluster.global.mbarrier::complete_tx::bytes " \
                 "[%0], [%1], %2, [%3];" \
                 :: "r"(dst), "l"(src), "r"((uint32_t)(bytes)), "r"(mb) : "memory")

#define LDSM_X4(r, addr) \
    asm volatile("ldmatrix.sync.aligned.m8n8.x4.shared.b16 {%0,%1,%2,%3}, [%4];" \
        : "=r"((r)[0]), "=r"((r)[1]), "=r"((r)[2]), "=r"((r)[3]) : "r"(addr))

#define MMA_BF16(c, a, b0, b1) \
    asm volatile("mma.sync.aligned.m16n8k16.row.col.f32.bf16.bf16.f32 " \
        "{%0,%1,%2,%3}, {%4,%5,%6,%7}, {%8,%9}, {%0,%1,%2,%3};" \
        : "+f"((c)[0]), "+f"((c)[1]), "+f"((c)[2]), "+f"((c)[3]) \
        : "r"((a)[0]), "r"((a)[1]), "r"((a)[2]), "r"((a)[3]), "r"(b0), "r"(b1))

__device__ __forceinline__ uint32_t pack_bf16(__nv_bfloat16 a, __nv_bfloat16 b) {
    __nv_bfloat162 t(a, b);
    return *reinterpret_cast<uint32_t*>(&t);
}
// blocked-SW128 word address (within g_candb / g_ebf) for (tile, row, pair q)
__device__ __forceinline__ size_t sw_word(int tile, int r, int q) {
    int c = q >> 5;
    int boff = r * 128 + 4 * (q & 31);
    int sw = boff ^ ((boff >> 3) & 0x70);
    return ((size_t)tile * TILE_BYTES + (size_t)c * CHUNK_BYTES + sw) >> 2;
}

// ---------------------------------------------------------------------------
// k_prep: fused detect + z/y/pad candidate copy (fp32 + swizzled bf16) +
// static keys + W transposes.  Grid 322 x 256.
// ---------------------------------------------------------------------------
__global__ void __launch_bounds__(256) k_prep(const float* __restrict__ z,
                                              const float* __restrict__ y,
                                              const float* __restrict__ Wst,
                                              const float* __restrict__ Wemit,
                                              const float* __restrict__ Wdyn,
                                              const int* __restrict__ yt32) {
    int b = blockIdx.x, tid = threadIdx.x;
    if (b < 192) {
        // candidate rows 256..639: fp32 copy + bf16 swizzled write (pairs)
        int idx, R;
        float2 v;
        if (b < 128) {                       // z -> rows 256..511
            idx = b * 256 + tid;             // pair index in [0, 32768)
            R = 256 + (idx >> 7);
            v = reinterpret_cast<const float2*>(z)[idx];
        } else if (b < 144) {                // y -> rows 512..543
            idx = (b - 128) * 256 + tid;     // [0, 4096)
            R = 512 + (idx >> 7);
            v = reinterpret_cast<const float2*>(y)[idx];
        } else {                             // pad rows 544..639
            idx = (b - 144) * 256 + tid;     // [0, 12288)
            R = 544 + (idx >> 7);
            v = make_float2(0.f, 0.f);
        }
        int q = idx & 127;
        reinterpret_cast<float2*>(g_cand)[(size_t)R * 128 + q] = v;
        g_candb[sw_word(R >> 7, R & 127, q)] =
            pack_bf16(__float2bfloat16_rn(v.x), __float2bfloat16_rn(v.y));
    } else if (b == 192) {
        // static key rows for both batches
        g_xkey[tid] = Wst[tid];
        g_xkey[256 + tid] = Wst[256 + tid];
        g_xkey[C_ * E_ + tid] = Wst[tid];
        g_xkey[C_ * E_ + 256 + tid] = Wst[256 + tid];
    } else if (b < 321) {
        // transpose Wemit (blocks 193..256) / Wdyn (257..320), 32x32 tiles
        __shared__ float sm[32][33];
        int t = (b < 257) ? (b - 193) : (b - 257);
        const float* W = (b < 257) ? Wemit : Wdyn;
        float* Wt = (b < 257) ? g_wtE : g_wtD;
        int tr = t >> 3, tc = t & 7;
        int tx = tid & 31, ty = tid >> 5;
#pragma unroll
        for (int i = 0; i < 4; ++i)
            sm[ty + 8 * i][tx] = W[(size_t)(tr * 32 + ty + 8 * i) * E_ + tc * 32 + tx];
        __syncthreads();
#pragma unroll
        for (int i = 0; i < 4; ++i)
            Wt[(size_t)(tc * 32 + ty + 8 * i) * E_ + tr * 32 + tx] = sm[tx][ty + 8 * i];
    } else {
        // detect yt dtype from odd-word zero pattern (in-bounds either way)
        __shared__ int ok;
        if (tid == 0) ok = 1;
        __syncthreads();
        if (tid < 128 && yt32[2 * tid + 1] != 0) atomicExch(&ok, 0);
        __syncthreads();
        if (tid == 0) g_yt64 = ok;
    }
}

// ---------------------------------------------------------------------------
// k_smallgemm: 8 output rows per block, coalesced W^T reads.
// blocks 0..31: emit = xsa @ Wemit^T + b  -> g_cand rows [0,256) + g_candb
// blocks 32..35: dyn keys = y @ Wdyn^T + b -> g_xkey
// ---------------------------------------------------------------------------
__global__ void __launch_bounds__(256) k_smallgemm(const float* __restrict__ xsa,
                                                   const float* __restrict__ y,
                                                   const float* __restrict__ bemit,
                                                   const float* __restrict__ bdyn) {
    __shared__ float4 As2[E_][2];            // [k][r/4] : 8 row-values per k
    int blk = blockIdx.x, tid = threadIdx.x;
    int m0 = blk * 8;
    bool dyn = (m0 >= 256);
    const float* Asrc = dyn ? (y + (size_t)(m0 - 256) * E_) : (xsa + (size_t)m0 * E_);
    const float* Wt = dyn ? g_wtD : g_wtE;
    const float* bias = dyn ? bdyn : bemit;

    float* As2f = reinterpret_cast<float*>(As2);
#pragma unroll
    for (int r = 0; r < 8; ++r) As2f[tid * 8 + r] = Asrc[(size_t)r * E_ + tid];
    __syncthreads();

    float acc[8];
    float bv = bias[tid];
#pragma unroll
    for (int r = 0; r < 8; ++r) acc[r] = bv;
#pragma unroll 4
    for (int k = 0; k < E_; ++k) {
        float w = Wt[(size_t)k * E_ + tid];
        float4 a0 = As2[k][0], a1 = As2[k][1];
        acc[0] = fmaf(a0.x, w, acc[0]);
        acc[1] = fmaf(a0.y, w, acc[1]);
        acc[2] = fmaf(a0.z, w, acc[2]);
        acc[3] = fmaf(a0.w, w, acc[3]);
        acc[4] = fmaf(a1.x, w, acc[4]);
        acc[5] = fmaf(a1.y, w, acc[5]);
        acc[6] = fmaf(a1.z, w, acc[6]);
        acc[7] = fmaf(a1.w, w, acc[7]);
    }

    if (!dyn) {
#pragma unroll
        for (int r = 0; r < 8; ++r) {
            int row = m0 + r;
            g_cand[(size_t)row * E_ + tid] = acc[r];
            float other = __shfl_xor_sync(0xffffffffu, acc[r], 1);
            if (!(tid & 1)) {
                g_candb[sw_word(row >> 7, row & 127, tid >> 1)] =
                    pack_bf16(__float2bfloat16_rn(acc[r]), __float2bfloat16_rn(other));
            }
        }
    } else {
#pragma unroll
        for (int r = 0; r < 8; ++r) {
            int d = m0 - 256 + r;
            int bb = d >> 4, j = d & 15;
            g_xkey[(size_t)(bb * C_ + 2 + j) * E_ + tid] = acc[r];
        }
    }
}

// ---------------------------------------------------------------------------
// Convert embed fp32 -> bf16 in blocked SW128 tile layout.
// ---------------------------------------------------------------------------
__global__ void __launch_bounds__(256) k_convert(const float* __restrict__ embed) {
    int idx = blockIdx.x * 256 + threadIdx.x;          // 0 .. 4,095,999
    int v = idx >> 7;
    int q = idx & 127;
    float2 x = reinterpret_cast<const float2*>(embed)[(size_t)v * 128 + q];
    g_ebf[sw_word(v >> 7, v & 127, q)] =
        pack_bf16(__float2bfloat16_rn(x.x), __float2bfloat16_rn(x.y));
}

// ---------------------------------------------------------------------------
// Main GEMM+exp-sum kernel. Grid (5 mt, 125 vt-pairs). Per CTA: A tile loaded
// once (64KB), two vocab tiles processed with double-buffered B (2x64KB).
// Inner loop: 8 warps 2m x 4n, mma.sync.m16n8k16, SW128 ldmatrix.
// ---------------------------------------------------------------------------
__global__ void __launch_bounds__(256, 1) k_main() {
    extern __shared__ __align__(16) char smem_raw[];
    uint32_t sb = smem_u32(smem_raw);
    uint32_t ab = (sb + 1023u) & ~1023u;
    uint32_t mb = ab;                        // barriers: A@+0, B0 chunks@+8.., B1@+40..
    uint32_t Abase = ab + 1024u;
    uint32_t B0 = Abase + TILE_BYTES;
    uint32_t B1 = B0 + TILE_BYTES;
    float* pssf = reinterpret_cast<float*>(smem_raw + ((B1 + TILE_BYTES) - sb));

    const int tid = threadIdx.x;
    const int lane = tid & 31, wid = tid >> 5;
    const int wm = wid & 1, wn = wid >> 1;
    const int mt = blockIdx.x;               // 0..4
    const int vt0 = blockIdx.y * 2;          // 0..248

    if (tid == 0)
        for (int s = 0; s < 9; ++s) MBARRIER_INIT(mb + 8 * s, 1);
    __syncthreads();
    if (tid == 0) {
        const char* asrc = reinterpret_cast<const char*>(g_candb) + (size_t)mt * TILE_BYTES;
        MBARRIER_EXPECT_TX(mb, TILE_BYTES);
        CP_ASYNC_BULK(Abase, asrc, TILE_BYTES, mb);
        const char* b0src = reinterpret_cast<const char*>(g_ebf) + (size_t)vt0 * TILE_BYTES;
        const char* b1src = b0src + TILE_BYTES;
        for (int s = 0; s < 4; ++s) {
            MBARRIER_EXPECT_TX(mb + 8 + 8 * s, CHUNK_BYTES);
            CP_ASYNC_BULK(B0 + s * CHUNK_BYTES, b0src + s * CHUNK_BYTES, CHUNK_BYTES, mb + 8 + 8 * s);
        }
        for (int s = 0; s < 4; ++s) {
            MBARRIER_EXPECT_TX(mb + 40 + 8 * s, CHUNK_BYTES);
            CP_ASYNC_BULK(B1 + s * CHUNK_BYTES, b1src + s * CHUNK_BYTES, CHUNK_BYTES, mb + 40 + 8 * s);
        }
    }

    // ldmatrix lane address parameters
    const int q = lane >> 3, j = lane & 7;
    const int a_row0 = wm * 64 + ((q & 1) << 3) + j;   // + mi*16
    const int a_kd = q >> 1;
    const int b_row0 = wn * 32 + ((q & 2) << 2) + j;   // + p*16
    const int b_kd = q & 1;
    const int g = lane >> 2, t4 = lane & 3;

    MBARRIER_WAIT(mb, 0);                    // A resident

#pragma unroll
    for (int it = 0; it < 2; ++it) {
        const uint32_t Bbase = it ? B1 : B0;
        const uint32_t mbB = mb + 8 + it * 32;

        float c[4][4][4];
#pragma unroll
        for (int mi = 0; mi < 4; ++mi)
#pragma unroll
            for (int nj = 0; nj < 4; ++nj)
#pragma unroll
                for (int e = 0; e < 4; ++e) c[mi][nj][e] = 0.f;

#pragma unroll
        for (int s = 0; s < 16; ++s) {
            if ((s & 3) == 0) MBARRIER_WAIT(mbB + 8 * (s >> 2), 0);
            const uint32_t Ac = Abase + (s >> 2) * CHUNK_BYTES;
            const uint32_t Bc = Bbase + (s >> 2) * CHUNK_BYTES;
            const int kg = (s & 3) * 2;

            uint32_t a[4][4];
#pragma unroll
            for (int mi = 0; mi < 4; ++mi) {
                int r = a_row0 + mi * 16;
                LDSM_X4(a[mi], Ac + r * 128 + (((kg + a_kd) ^ (r & 7)) << 4));
            }
            uint32_t bfr[2][4];
#pragma unroll
            for (int p = 0; p < 2; ++p) {
                int r = b_row0 + p * 16;
                LDSM_X4(bfr[p], Bc + r * 128 + (((kg + b_kd) ^ (r & 7)) << 4));
            }
#pragma unroll
            for (int mi = 0; mi < 4; ++mi)
#pragma unroll
                for (int p = 0; p < 2; ++p) {
                    MMA_BF16(c[mi][2 * p],     a[mi], bfr[p][0], bfr[p][1]);
                    MMA_BF16(c[mi][2 * p + 1], a[mi], bfr[p][2], bfr[p][3]);
                }
        }

        // Epilogue: per-row sum of exp(logit)
#pragma unroll
        for (int mi = 0; mi < 4; ++mi) {
            float sA = 0.f, sB = 0.f;
#pragma unroll
            for (int nj = 0; nj < 4; ++nj) {
                sA += __expf(c[mi][nj][0]) + __expf(c[mi][nj][1]);
                sB += __expf(c[mi][nj][2]) + __expf(c[mi][nj][3]);
            }
            sA += __shfl_xor_sync(0xffffffffu, sA, 1);
            sA += __shfl_xor_sync(0xffffffffu, sA, 2);
            sB += __shfl_xor_sync(0xffffffffu, sB, 1);
            sB += __shfl_xor_sync(0xffffffffu, sB, 2);
            if (t4 == 0) {
                int row = wm * 64 + mi * 16 + g;
                pssf[row * 4 + wn] = sA;
                pssf[(row + 8) * 4 + wn] = sB;
            }
        }
        __syncthreads();
        if (tid < BM) {
            float s = pssf[tid * 4] + pssf[tid * 4 + 1] + pssf[tid * 4 + 2] + pssf[tid * 4 + 3];
            g_partial[(size_t)(mt * BM + tid) * NVT_PAD + (vt0 + it)] = s;
        }
        __syncthreads();
    }
}

// ---------------------------------------------------------------------------
// Reduce per-row vocab-tile partials -> logZ[row]
// ---------------------------------------------------------------------------
__global__ void k_reduceZ() {
    int row = blockIdx.x;
    int tid = threadIdx.x;
    float v = (tid < NVT) ? g_partial[(size_t)row * NVT_PAD + tid] : 0.f;
#pragma unroll
    for (int o = 16; o > 0; o >>= 1) v += __shfl_xor_sync(0xffffffffu, v, o);
    __shared__ float sm[8];
    if ((tid & 31) == 0) sm[tid >> 5] = v;
    __syncthreads();
    if (tid == 0) {
        float s = 0.f;
#pragma unroll
        for (int w = 0; w < 8; ++w) s += sm[w];
        g_logZ[row] = logf(s);
    }
}

// ---------------------------------------------------------------------------
// Per (b,l): selection dots, target-logit dots, double LSE -> -cent
// ---------------------------------------------------------------------------
__global__ void __launch_bounds__(256) k_final(const float* __restrict__ xsa,
                                               const float* __restrict__ embed,
                                               const void* __restrict__ ytv) {
    int bl = blockIdx.x;            // 0..255
    int b = bl >> 7;
    int tid = threadIdx.x;

    long long t;
    if (g_yt64) t = ((const long long*)ytv)[bl];
    else        t = (long long)((const int*)ytv)[bl];

    float xv = xsa[(size_t)bl * E_ + tid];
    float ev = embed[(size_t)t * E_ + tid];

    float sv[C_], tv[C_];
#pragma unroll
    for (int c = 0; c < C_; ++c)
        sv[c] = xv * g_xkey[(size_t)(b * C_ + c) * E_ + tid];
    tv[0] = ev * g_cand[(size_t)bl * E_ + tid];
    tv[1] = ev * g_cand[(size_t)(256 + bl) * E_ + tid];
#pragma unroll
    for (int j = 0; j < LY_; ++j)
        tv[2 + j] = ev * g_cand[(size_t)(512 + b * LY_ + j) * E_ + tid];

    __shared__ float red[2 * C_][9];
    int lane = tid & 31, w = tid >> 5;
#pragma unroll
    for (int c = 0; c < C_; ++c) {
        float v = sv[c];
#pragma unroll
        for (int o = 16; o > 0; o >>= 1) v += __shfl_xor_sync(0xffffffffu, v, o);
        if (lane == 0) red[c][w] = v;
    }
#pragma unroll
    for (int c = 0; c < C_; ++c) {
        float v = tv[c];
#pragma unroll
        for (int o = 16; o > 0; o >>= 1) v += __shfl_xor_sync(0xffffffffu, v, o);
        if (lane == 0) red[C_ + c][w] = v;
    }
    __syncthreads();

    if (tid == 0) {
        float s[C_], tl[C_];
#pragma unroll
        for (int c = 0; c < C_; ++c) {
            float a0 = 0.f, a1 = 0.f;
#pragma unroll
            for (int ww = 0; ww < 8; ++ww) { a0 += red[c][ww]; a1 += red[C_ + c][ww]; }
            s[c] = a0; tl[c] = a1;
        }
        float qv[C_];
        qv[0] = s[0] + tl[0] - g_logZ[bl];
        qv[1] = s[1] + tl[1] - g_logZ[256 + bl];
#pragma unroll
        for (int j = 0; j < LY_; ++j)
            qv[2 + j] = s[2 + j] + tl[2 + j] - g_logZ[512 + b * LY_ + j];

        float ms = s[0], mq = qv[0];
#pragma unroll
        for (int c = 1; c < C_; ++c) { ms = fmaxf(ms, s[c]); mq = fmaxf(mq, qv[c]); }
        float ss = 0.f, sq = 0.f;
#pragma unroll
        for (int c = 0; c < C_; ++c) { ss += expf(s[c] - ms); sq += expf(qv[c] - mq); }
        g_negcent[bl] = -((mq + logf(sq)) - (ms + logf(ss)));
    }
}

// ---------------------------------------------------------------------------
__global__ void k_out(float* __restrict__ out) {
    __shared__ float sm[B_ * L_];
    int tid = threadIdx.x;
    sm[tid] = g_negcent[tid];
    __syncthreads();
    if (tid < B_) {
        float s = 0.f;
        for (int i = 0; i < L_; ++i) s += sm[tid * L_ + i];
        out[tid] = s / (float)L_;
    }
}

// ---------------------------------------------------------------------------
extern "C" void kernel_launch(void* const* d_in, const int* in_sizes, int n_in,
                              void* d_out, int out_size) {
    const float* xsa   = (const float*)d_in[0];
    const float* z     = (const float*)d_in[1];
    const float* y     = (const float*)d_in[2];
    const void*  yt    = d_in[3];
    const float* embed = (const float*)d_in[4];
    const float* Wst   = (const float*)d_in[5];
    const float* Wdyn  = (const float*)d_in[6];
    const float* bdyn  = (const float*)d_in[7];
    const float* Wemit = (const float*)d_in[8];
    const float* bemit = (const float*)d_in[9];
    float* out = (float*)d_out;

    cudaFuncSetAttribute(k_main, cudaFuncAttributeMaxDynamicSharedMemorySize,
                         SMEM_REQ);

    k_prep<<<322, 256>>>(z, y, Wst, Wemit, Wdyn, (const int*)yt);
    k_smallgemm<<<36, 256>>>(xsa, y, bemit, bdyn);
    k_convert<<<16000, 256>>>(embed);
    k_main<<<dim3(NMT, NVT / 2), 256, SMEM_REQ>>>();
    k_reduceZ<<<R_, 256>>>();
    k_final<<<B_ * L_, 256>>>(xsa, embed, yt);
    k_out<<<1, 256>>>(out);
}

// round 7
// speedup vs baseline: 3.4326x; 1.0760x over previous
#include <cuda_runtime.h>
#include <cuda_bf16.h>
#include <math.h>
#include <stdint.h>

// ---------------- problem constants ----------------
#define B_   2
#define L_   128
#define LY_  16
#define E_   256
#define V_   32000
#define C_   18        // 2 static + LY dynamic mixture components

// Distinct candidate rows: 0..255 emit(b,l), 256..511 z(b,l), 512..543 y(b,j)
#define R_      544
#define RPAD    640    // 5 tiles of 128
#define BM      128
#define NMT     5      // RPAD/BM
#define NVT     250    // V_/128
#define NVT_PAD 256

#define TILE_BYTES  65536     // one 128-row x 256-k bf16 tile (blocked SW128)
#define CHUNK_BYTES 16384     // one k64 chunk (128 rows x 128B)
// 1023 slack + 1024 ctrl + A(64K) + B0(64K) + B1(64K) + pss(4K)
#define SMEM_REQ    202752

#define NCONV 16000           // convert blocks inside k_prep

// ---------------- device scratch (no allocation allowed) ----------------
__device__ float    g_cand[RPAD * E_];
__device__ float    g_xkey[B_ * C_ * E_];
__device__ float    g_partial[RPAD * NVT_PAD];
__device__ float    g_negcent[B_ * L_];
__device__ int      g_yt64;
__device__ float    g_wtE[E_ * E_];                         // Wemit^T
__device__ float    g_wtD[E_ * E_];                         // Wdyn^T
__device__ uint32_t g_candb[NMT * TILE_BYTES / 4];          // cand bf16, swizzled
__device__ uint32_t g_ebf[(size_t)NVT * TILE_BYTES / 4];    // embed bf16, swizzled

// ---------------- PTX helpers (plain sm_100-safe) ----------
__device__ __forceinline__ uint32_t smem_u32(const void* p) {
    uint32_t a;
    asm("{ .reg .u64 t; cvta.to.shared.u64 t, %1; cvt.u32.u64 %0, t; }"
        : "=r"(a) : "l"(p));
    return a;
}
#define MBARRIER_INIT(mb, cnt) \
    asm volatile("mbarrier.init.shared.b64 [%0], %1;" :: "r"(mb), "r"((uint32_t)(cnt)) : "memory")
#define MBARRIER_EXPECT_TX(mb, bytes) \
    asm volatile("mbarrier.arrive.expect_tx.shared.b64 _, [%0], %1;" \
                 :: "r"(mb), "r"((uint32_t)(bytes)) : "memory")
#define MBARRIER_WAIT(mb, ph) do {                                              \
    uint32_t _mb = (mb), _ph = (ph), _done;                                     \
    asm volatile("{\n\t.reg .pred p;\n\t"                                       \
        "mbarrier.try_wait.parity.acquire.cta.shared::cta.b64 p, [%1], %2;\n\t" \
        "selp.b32 %0, 1, 0, p;\n\t}" : "=r"(_done) : "r"(_mb), "r"(_ph) : "memory"); \
    if (!_done) {                                                               \
        asm volatile("{\n\t.reg .pred P1;\n\t"                                  \
            "WL_%=:\n\t"                                                        \
            "mbarrier.try_wait.parity.acquire.cta.shared::cta.b64 P1, [%0], %1, 0x989680;\n\t" \
            "@P1 bra.uni WD_%=;\n\t"                                            \
            "bra.uni WL_%=;\n\t"                                                \
            "WD_%=:\n\t}" :: "r"(_mb), "r"(_ph) : "memory");                    \
    }                                                                           \
} while (0)
#define CP_ASYNC_BULK(dst, src, bytes, mb) \
    asm volatile("cp.async.bulk.shared::cluster.global.mbarrier::complete_tx::bytes " \
                 "[%0], [%1], %2, [%3];" \
                 :: "r"(dst), "l"(src), "r"((uint32_t)(bytes)), "r"(mb) : "memory")

#define LDSM_X4(r, addr) \
    asm volatile("ldmatrix.sync.aligned.m8n8.x4.shared.b16 {%0,%1,%2,%3}, [%4];" \
        : "=r"((r)[0]), "=r"((r)[1]), "=r"((r)[2]), "=r"((r)[3]) : "r"(addr))

#define MMA_BF16(c, a, b0, b1) \
    asm volatile("mma.sync.aligned.m16n8k16.row.col.f32.bf16.bf16.f32 " \
        "{%0,%1,%2,%3}, {%4,%5,%6,%7}, {%8,%9}, {%0,%1,%2,%3};" \
        : "+f"((c)[0]), "+f"((c)[1]), "+f"((c)[2]), "+f"((c)[3]) \
        : "r"((a)[0]), "r"((a)[1]), "r"((a)[2]), "r"((a)[3]), "r"(b0), "r"(b1))

__device__ __forceinline__ uint32_t pack_bf16(__nv_bfloat16 a, __nv_bfloat16 b) {
    __nv_bfloat162 t(a, b);
    return *reinterpret_cast<uint32_t*>(&t);
}
// blocked-SW128 word address (within g_candb / g_ebf) for (tile, row, pair q)
__device__ __forceinline__ size_t sw_word(int tile, int r, int q) {
    int c = q >> 5;
    int boff = r * 128 + 4 * (q & 31);
    int sw = boff ^ ((boff >> 3) & 0x70);
    return ((size_t)tile * TILE_BYTES + (size_t)c * CHUNK_BYTES + sw) >> 2;
}

// ---------------------------------------------------------------------------
// k_prep: fused embed-conversion + detect + z/y/pad candidate copy (fp32 +
// swizzled bf16) + static keys + W transposes. Grid NCONV+322 x 256.
// ---------------------------------------------------------------------------
__global__ void __launch_bounds__(256) k_prep(const float* __restrict__ z,
                                              const float* __restrict__ y,
                                              const float* __restrict__ Wst,
                                              const float* __restrict__ Wemit,
                                              const float* __restrict__ Wdyn,
                                              const int* __restrict__ yt32,
                                              const float* __restrict__ embed) {
    int bx = blockIdx.x, tid = threadIdx.x;
    if (bx < NCONV) {
        // embed fp32 -> bf16 blocked SW128
        int idx = bx * 256 + tid;                      // 0 .. 4,095,999
        int v = idx >> 7;
        int q = idx & 127;
        float2 x = reinterpret_cast<const float2*>(embed)[(size_t)v * 128 + q];
        g_ebf[sw_word(v >> 7, v & 127, q)] =
            pack_bf16(__float2bfloat16_rn(x.x), __float2bfloat16_rn(x.y));
        return;
    }
    int b = bx - NCONV;
    if (b < 192) {
        // candidate rows 256..639: fp32 copy + bf16 swizzled write (pairs)
        int idx, R;
        float2 v;
        if (b < 128) {                       // z -> rows 256..511
            idx = b * 256 + tid;
            R = 256 + (idx >> 7);
            v = reinterpret_cast<const float2*>(z)[idx];
        } else if (b < 144) {                // y -> rows 512..543
            idx = (b - 128) * 256 + tid;
            R = 512 + (idx >> 7);
            v = reinterpret_cast<const float2*>(y)[idx];
        } else {                             // pad rows 544..639
            idx = (b - 144) * 256 + tid;
            R = 544 + (idx >> 7);
            v = make_float2(0.f, 0.f);
        }
        int q = idx & 127;
        reinterpret_cast<float2*>(g_cand)[(size_t)R * 128 + q] = v;
        g_candb[sw_word(R >> 7, R & 127, q)] =
            pack_bf16(__float2bfloat16_rn(v.x), __float2bfloat16_rn(v.y));
    } else if (b == 192) {
        g_xkey[tid] = Wst[tid];
        g_xkey[256 + tid] = Wst[256 + tid];
        g_xkey[C_ * E_ + tid] = Wst[tid];
        g_xkey[C_ * E_ + 256 + tid] = Wst[256 + tid];
    } else if (b < 321) {
        // transpose Wemit (193..256) / Wdyn (257..320), 32x32 tiles
        __shared__ float sm[32][33];
        int t = (b < 257) ? (b - 193) : (b - 257);
        const float* W = (b < 257) ? Wemit : Wdyn;
        float* Wt = (b < 257) ? g_wtE : g_wtD;
        int tr = t >> 3, tc = t & 7;
        int tx = tid & 31, ty = tid >> 5;
#pragma unroll
        for (int i = 0; i < 4; ++i)
            sm[ty + 8 * i][tx] = W[(size_t)(tr * 32 + ty + 8 * i) * E_ + tc * 32 + tx];
        __syncthreads();
#pragma unroll
        for (int i = 0; i < 4; ++i)
            Wt[(size_t)(tc * 32 + ty + 8 * i) * E_ + tr * 32 + tx] = sm[tx][ty + 8 * i];
    } else {
        // detect yt dtype from odd-word zero pattern (in-bounds either way)
        __shared__ int ok;
        if (tid == 0) ok = 1;
        __syncthreads();
        if (tid < 128 && yt32[2 * tid + 1] != 0) atomicExch(&ok, 0);
        __syncthreads();
        if (tid == 0) g_yt64 = ok;
    }
}

// ---------------------------------------------------------------------------
// k_smallgemm: 8 output rows per block, coalesced W^T reads.
// blocks 0..31: emit = xsa @ Wemit^T + b  -> g_cand rows [0,256) + g_candb
// blocks 32..35: dyn keys = y @ Wdyn^T + b -> g_xkey
// ---------------------------------------------------------------------------
__global__ void __launch_bounds__(256) k_smallgemm(const float* __restrict__ xsa,
                                                   const float* __restrict__ y,
                                                   const float* __restrict__ bemit,
                                                   const float* __restrict__ bdyn) {
    __shared__ float4 As2[E_][2];
    int blk = blockIdx.x, tid = threadIdx.x;
    int m0 = blk * 8;
    bool dyn = (m0 >= 256);
    const float* Asrc = dyn ? (y + (size_t)(m0 - 256) * E_) : (xsa + (size_t)m0 * E_);
    const float* Wt = dyn ? g_wtD : g_wtE;
    const float* bias = dyn ? bdyn : bemit;

    float* As2f = reinterpret_cast<float*>(As2);
#pragma unroll
    for (int r = 0; r < 8; ++r) As2f[tid * 8 + r] = Asrc[(size_t)r * E_ + tid];
    __syncthreads();

    float acc[8];
    float bv = bias[tid];
#pragma unroll
    for (int r = 0; r < 8; ++r) acc[r] = bv;
#pragma unroll 4
    for (int k = 0; k < E_; ++k) {
        float w = Wt[(size_t)k * E_ + tid];
        float4 a0 = As2[k][0], a1 = As2[k][1];
        acc[0] = fmaf(a0.x, w, acc[0]);
        acc[1] = fmaf(a0.y, w, acc[1]);
        acc[2] = fmaf(a0.z, w, acc[2]);
        acc[3] = fmaf(a0.w, w, acc[3]);
        acc[4] = fmaf(a1.x, w, acc[4]);
        acc[5] = fmaf(a1.y, w, acc[5]);
        acc[6] = fmaf(a1.z, w, acc[6]);
        acc[7] = fmaf(a1.w, w, acc[7]);
    }

    if (!dyn) {
#pragma unroll
        for (int r = 0; r < 8; ++r) {
            int row = m0 + r;
            g_cand[(size_t)row * E_ + tid] = acc[r];
            float other = __shfl_xor_sync(0xffffffffu, acc[r], 1);
            if (!(tid & 1)) {
                g_candb[sw_word(row >> 7, row & 127, tid >> 1)] =
                    pack_bf16(__float2bfloat16_rn(acc[r]), __float2bfloat16_rn(other));
            }
        }
    } else {
#pragma unroll
        for (int r = 0; r < 8; ++r) {
            int d = m0 - 256 + r;
            int bb = d >> 4, j = d & 15;
            g_xkey[(size_t)(bb * C_ + 2 + j) * E_ + tid] = acc[r];
        }
    }
}

// ---------------------------------------------------------------------------
// Main GEMM+exp-sum kernel. Grid (5 mt, 125 vt-pairs). Per CTA: A tile loaded
// once, BOTH vocab tiles of the pair processed in ONE k-loop so each A
// fragment (ldmatrix) feeds MMAs for both B halves: 8 LDSM per 32 MMA.
// ---------------------------------------------------------------------------
__global__ void __launch_bounds__(256, 1) k_main() {
    extern __shared__ __align__(16) char smem_raw[];
    uint32_t sb = smem_u32(smem_raw);
    uint32_t ab = (sb + 1023u) & ~1023u;
    uint32_t mb = ab;                        // A barrier @+0, chunk barriers @+8..+32
    uint32_t Abase = ab + 1024u;
    uint32_t B0 = Abase + TILE_BYTES;
    uint32_t B1 = B0 + TILE_BYTES;
    float* pssf = reinterpret_cast<float*>(smem_raw + ((B1 + TILE_BYTES) - sb)); // [2][128][4]

    const int tid = threadIdx.x;
    const int lane = tid & 31, wid = tid >> 5;
    const int wm = wid & 1, wn = wid >> 1;
    const int mt = blockIdx.x;               // 0..4
    const int vt0 = blockIdx.y * 2;          // 0..248

    if (tid == 0)
        for (int s = 0; s < 5; ++s) MBARRIER_INIT(mb + 8 * s, 1);
    __syncthreads();
    if (tid == 0) {
        const char* asrc = reinterpret_cast<const char*>(g_candb) + (size_t)mt * TILE_BYTES;
        MBARRIER_EXPECT_TX(mb, TILE_BYTES);
        CP_ASYNC_BULK(Abase, asrc, TILE_BYTES, mb);
        const char* b0src = reinterpret_cast<const char*>(g_ebf) + (size_t)vt0 * TILE_BYTES;
        const char* b1src = b0src + TILE_BYTES;
        for (int s = 0; s < 4; ++s) {
            MBARRIER_EXPECT_TX(mb + 8 + 8 * s, 2 * CHUNK_BYTES);
            CP_ASYNC_BULK(B0 + s * CHUNK_BYTES, b0src + s * CHUNK_BYTES, CHUNK_BYTES, mb + 8 + 8 * s);
            CP_ASYNC_BULK(B1 + s * CHUNK_BYTES, b1src + s * CHUNK_BYTES, CHUNK_BYTES, mb + 8 + 8 * s);
        }
    }

    // ldmatrix lane address parameters
    const int q = lane >> 3, j = lane & 7;
    const int a_row0 = wm * 64 + ((q & 1) << 3) + j;   // + mi*16
    const int a_kd = q >> 1;
    const int b_row0 = wn * 32 + ((q & 2) << 2) + j;   // + p*16
    const int b_kd = q & 1;
    const int g = lane >> 2, t4 = lane & 3;

    float c[2][4][4][4];
#pragma unroll
    for (int h = 0; h < 2; ++h)
#pragma unroll
        for (int mi = 0; mi < 4; ++mi)
#pragma unroll
            for (int nj = 0; nj < 4; ++nj)
#pragma unroll
                for (int e = 0; e < 4; ++e) c[h][mi][nj][e] = 0.f;

    MBARRIER_WAIT(mb, 0);                    // A resident

#pragma unroll
    for (int s = 0; s < 16; ++s) {
        if ((s & 3) == 0) MBARRIER_WAIT(mb + 8 + 8 * (s >> 2), 0);
        const uint32_t Ac = Abase + (s >> 2) * CHUNK_BYTES;
        const uint32_t Bc0 = B0 + (s >> 2) * CHUNK_BYTES;
        const uint32_t Bc1 = B1 + (s >> 2) * CHUNK_BYTES;
        const int kg = (s & 3) * 2;

        uint32_t a[4][4];
#pragma unroll
        for (int mi = 0; mi < 4; ++mi) {
            int r = a_row0 + mi * 16;
            LDSM_X4(a[mi], Ac + r * 128 + (((kg + a_kd) ^ (r & 7)) << 4));
        }
        uint32_t bf0[2][4], bf1[2][4];
#pragma unroll
        for (int p = 0; p < 2; ++p) {
            int r = b_row0 + p * 16;
            uint32_t off = r * 128 + (((kg + b_kd) ^ (r & 7)) << 4);
            LDSM_X4(bf0[p], Bc0 + off);
            LDSM_X4(bf1[p], Bc1 + off);
        }
#pragma unroll
        for (int mi = 0; mi < 4; ++mi)
#pragma unroll
            for (int p = 0; p < 2; ++p) {
                MMA_BF16(c[0][mi][2 * p],     a[mi], bf0[p][0], bf0[p][1]);
                MMA_BF16(c[0][mi][2 * p + 1], a[mi], bf0[p][2], bf0[p][3]);
                MMA_BF16(c[1][mi][2 * p],     a[mi], bf1[p][0], bf1[p][1]);
                MMA_BF16(c[1][mi][2 * p + 1], a[mi], bf1[p][2], bf1[p][3]);
            }
    }

    // Epilogue: per-row sum of exp(logit) for both halves
#pragma unroll
    for (int h = 0; h < 2; ++h)
#pragma unroll
        for (int mi = 0; mi < 4; ++mi) {
            float sA = 0.f, sB = 0.f;
#pragma unroll
            for (int nj = 0; nj < 4; ++nj) {
                sA += __expf(c[h][mi][nj][0]) + __expf(c[h][mi][nj][1]);
                sB += __expf(c[h][mi][nj][2]) + __expf(c[h][mi][nj][3]);
            }
            sA += __shfl_xor_sync(0xffffffffu, sA, 1);
            sA += __shfl_xor_sync(0xffffffffu, sA, 2);
            sB += __shfl_xor_sync(0xffffffffu, sB, 1);
            sB += __shfl_xor_sync(0xffffffffu, sB, 2);
            if (t4 == 0) {
                int row = wm * 64 + mi * 16 + g;
                pssf[h * 512 + row * 4 + wn] = sA;
                pssf[h * 512 + (row + 8) * 4 + wn] = sB;
            }
        }
    __syncthreads();
    {
        int h = tid >> 7, row = tid & 127;
        const float* p = pssf + h * 512 + row * 4;
        g_partial[(size_t)(mt * BM + row) * NVT_PAD + (vt0 + h)] =
            p[0] + p[1] + p[2] + p[3];
    }
}

// ---------------------------------------------------------------------------
// Per (b,l): inline logZ reduction (18 rows x 250 partials), selection dots,
// target-logit dots, double LSE -> -cent
// ---------------------------------------------------------------------------
__global__ void __launch_bounds__(256) k_final(const float* __restrict__ xsa,
                                               const float* __restrict__ embed,
                                               const void* __restrict__ ytv) {
    int bl = blockIdx.x;            // 0..255
    int b = bl >> 7;
    int tid = threadIdx.x;
    int lane = tid & 31, w = tid >> 5;

    // inline reduceZ: 18 rows, warps 0..7 cover c = w, w+8, w+16
    __shared__ float lZ[C_];
#pragma unroll
    for (int c = w; c < C_; c += 8) {
        int row = (c == 0) ? bl : (c == 1) ? (256 + bl) : (512 + b * LY_ + (c - 2));
        float v = 0.f;
        for (int i = lane; i < NVT; i += 32) v += g_partial[(size_t)row * NVT_PAD + i];
#pragma unroll
        for (int o = 16; o > 0; o >>= 1) v += __shfl_xor_sync(0xffffffffu, v, o);
        if (lane == 0) lZ[c] = logf(v);
    }

    long long t;
    if (g_yt64) t = ((const long long*)ytv)[bl];
    else        t = (long long)((const int*)ytv)[bl];

    float xv = xsa[(size_t)bl * E_ + tid];
    float ev = embed[(size_t)t * E_ + tid];

    float sv[C_], tv[C_];
#pragma unroll
    for (int c = 0; c < C_; ++c)
        sv[c] = xv * g_xkey[(size_t)(b * C_ + c) * E_ + tid];
    tv[0] = ev * g_cand[(size_t)bl * E_ + tid];
    tv[1] = ev * g_cand[(size_t)(256 + bl) * E_ + tid];
#pragma unroll
    for (int j = 0; j < LY_; ++j)
        tv[2 + j] = ev * g_cand[(size_t)(512 + b * LY_ + j) * E_ + tid];

    __shared__ float red[2 * C_][9];
#pragma unroll
    for (int c = 0; c < C_; ++c) {
        float v = sv[c];
#pragma unroll
        for (int o = 16; o > 0; o >>= 1) v += __shfl_xor_sync(0xffffffffu, v, o);
        if (lane == 0) red[c][w] = v;
    }
#pragma unroll
    for (int c = 0; c < C_; ++c) {
        float v = tv[c];
#pragma unroll
        for (int o = 16; o > 0; o >>= 1) v += __shfl_xor_sync(0xffffffffu, v, o);
        if (lane == 0) red[C_ + c][w] = v;
    }
    __syncthreads();

    if (tid == 0) {
        float s[C_], tl[C_];
#pragma unroll
        for (int c = 0; c < C_; ++c) {
            float a0 = 0.f, a1 = 0.f;
#pragma unroll
            for (int ww = 0; ww < 8; ++ww) { a0 += red[c][ww]; a1 += red[C_ + c][ww]; }
            s[c] = a0; tl[c] = a1;
        }
        float qv[C_];
#pragma unroll
        for (int c = 0; c < C_; ++c) qv[c] = s[c] + tl[c] - lZ[c];

        float ms = s[0], mq = qv[0];
#pragma unroll
        for (int c = 1; c < C_; ++c) { ms = fmaxf(ms, s[c]); mq = fmaxf(mq, qv[c]); }
        float ss = 0.f, sq = 0.f;
#pragma unroll
        for (int c = 0; c < C_; ++c) { ss += expf(s[c] - ms); sq += expf(qv[c] - mq); }
        g_negcent[bl] = -((mq + logf(sq)) - (ms + logf(ss)));
    }
}

// ---------------------------------------------------------------------------
__global__ void k_out(float* __restrict__ out) {
    __shared__ float sm[B_ * L_];
    int tid = threadIdx.x;
    sm[tid] = g_negcent[tid];
    __syncthreads();
    if (tid < B_) {
        float s = 0.f;
        for (int i = 0; i < L_; ++i) s += sm[tid * L_ + i];
        out[tid] = s / (float)L_;
    }
}

// ---------------------------------------------------------------------------
extern "C" void kernel_launch(void* const* d_in, const int* in_sizes, int n_in,
                              void* d_out, int out_size) {
    const float* xsa   = (const float*)d_in[0];
    const float* z     = (const float*)d_in[1];
    const float* y     = (const float*)d_in[2];
    const void*  yt    = d_in[3];
    const float* embed = (const float*)d_in[4];
    const float* Wst   = (const float*)d_in[5];
    const float* Wdyn  = (const float*)d_in[6];
    const float* bdyn  = (const float*)d_in[7];
    const float* Wemit = (const float*)d_in[8];
    const float* bemit = (const float*)d_in[9];
    float* out = (float*)d_out;

    cudaFuncSetAttribute(k_main, cudaFuncAttributeMaxDynamicSharedMemorySize,
                         SMEM_REQ);

    k_prep<<<NCONV + 322, 256>>>(z, y, Wst, Wemit, Wdyn, (const int*)yt, embed);
    k_smallgemm<<<36, 256>>>(xsa, y, bemit, bdyn);
    k_main<<<dim3(NMT, NVT / 2), 256, SMEM_REQ>>>();
    k_final<<<B_ * L_, 256>>>(xsa, embed, yt);
    k_out<<<1, 256>>>(out);
}